// round 2
// baseline (speedup 1.0000x reference)
#include <cuda_runtime.h>
#include <math.h>

#define T_TOK 4096
#define D_IN  1024
#define H_HID 768
#define NE    23
#define TOPK  3
#define P_TOT (T_TOK * TOPK)

// ---------------- scratch (static device allocations) ----------------
__device__ float g_H [(size_t)P_TOT * H_HID];   // expert hidden (permuted order)
__device__ float g_Y [(size_t)P_TOT * D_IN];    // expert output (permuted order)
__device__ float g_Hs[(size_t)T_TOK * H_HID];   // shared-expert hidden
__device__ int   g_rows[P_TOT];                 // permuted position -> token id
__device__ int   g_tok_e [P_TOT];               // token,k -> expert
__device__ float g_tok_w [P_TOT];               // token,k -> normalized weight
__device__ int   g_tok_pos[P_TOT];              // token,k -> permuted position
__device__ int   g_counts[NE];
__device__ int   g_cursor[NE];
__device__ int   g_offs[NE + 1];
__device__ float g_Psum[NE];
__device__ int   g_soffs[2];

// ---------------- zero/init ----------------
__global__ void k_zero() {
    int i = threadIdx.x;
    if (i < NE) { g_counts[i] = 0; g_cursor[i] = 0; g_Psum[i] = 0.f; }
    if (i == 0) { g_soffs[0] = 0; g_soffs[1] = T_TOK; }
}

// ---------------- gating: logits, sigmoid, top-3, P accumulation ----------------
__global__ void __launch_bounds__(256) k_gate(const float* __restrict__ x,
                                              const float* __restrict__ gW,
                                              const float* __restrict__ gb,
                                              const float* __restrict__ bias) {
    __shared__ float xs[8][D_IN];
    __shared__ float sg[8][NE + 1];
    __shared__ float ss[8][NE + 1];
    int tid = threadIdx.x;
    int t0 = blockIdx.x * 8;
    for (int i = tid; i < 8 * D_IN; i += 256)
        ((float*)xs)[i] = x[(size_t)t0 * D_IN + i];
    __syncthreads();

    int w = tid >> 5, lane = tid & 31;
    int t = t0 + w;

    float gate = 0.f;
    if (lane < NE) {
        float acc = 0.f;
#pragma unroll 4
        for (int d = 0; d < D_IN; ++d)
            acc = fmaf(xs[w][d], gW[d * NE + lane], acc);
        acc += gb[lane];
        gate = 1.0f / (1.0f + expf(-acc));
        sg[w][lane] = gate;
        ss[w][lane] = gate + bias[lane];
    }
    // sum of gates across 23 lanes (for load-balance P)
    float v = (lane < NE) ? gate : 0.f;
#pragma unroll
    for (int o = 16; o > 0; o >>= 1) v += __shfl_xor_sync(0xffffffffu, v, o);
    if (lane < NE) atomicAdd(&g_Psum[lane], gate / v);
    __syncwarp();

    if (lane == 0) {
        int  idx[TOPK];
        float wv[TOPK];
        bool used[NE];
#pragma unroll
        for (int e = 0; e < NE; ++e) used[e] = false;
        float wsum = 0.f;
        for (int k = 0; k < TOPK; ++k) {
            int best = 0; float bs = -1e30f;
            for (int e = 0; e < NE; ++e)
                if (!used[e] && ss[w][e] > bs) { bs = ss[w][e]; best = e; }
            used[best] = true;
            idx[k] = best;
            wv[k] = sg[w][best];
            wsum += wv[k];
        }
        for (int k = 0; k < TOPK; ++k) {
            g_tok_e[t * TOPK + k] = idx[k];
            g_tok_w[t * TOPK + k] = wv[k] / wsum;
            atomicAdd(&g_counts[idx[k]], 1);
        }
    }
}

// ---------------- prefix sum over 23 experts ----------------
__global__ void k_prefix() {
    int o = 0;
    g_offs[0] = 0;
    for (int e = 0; e < NE; ++e) { o += g_counts[e]; g_offs[e + 1] = o; }
}

// ---------------- scatter tokens to per-expert contiguous lists ----------------
__global__ void k_scatter() {
    int t = blockIdx.x * blockDim.x + threadIdx.x;
    if (t >= T_TOK) return;
#pragma unroll
    for (int k = 0; k < TOPK; ++k) {
        int e = g_tok_e[t * TOPK + k];
        int p = g_offs[e] + atomicAdd(&g_cursor[e], 1);
        g_rows[p] = t;
        g_tok_pos[t * TOPK + k] = p;
    }
}

// ---------------- grouped tiled fp32 GEMM (+bias, optional exact GELU) ---------
// C[base+m, :] = act( A[row(m), :] @ W_e + bias_e ), m in [0, cnt)
template <bool GELU>
__global__ void __launch_bounds__(256) k_gemm(
    const float* __restrict__ A, const int* __restrict__ rows, int lda,
    const float* __restrict__ Wg, size_t wstride,
    const float* __restrict__ biasg, int bstride,
    float* __restrict__ C, int ldc,
    const int* __restrict__ offs, int Kd, int N)
{
    __shared__ float As[16][65];
    __shared__ __align__(16) float Bs[16][68];

    int e = blockIdx.z;
    int base = offs[e];
    int cnt  = offs[e + 1] - base;
    int m0 = blockIdx.y * 64;
    if (m0 >= cnt) return;
    int n0 = blockIdx.x * 64;

    const float* W  = Wg + (size_t)e * wstride;
    const float* bv = biasg + (size_t)e * bstride;

    int tid  = threadIdx.x;
    int arow = tid >> 2, acol = (tid & 3) << 2;   // A: 64 rows x 16 cols
    int brow = tid >> 4, bcol = (tid & 15) << 2;  // B: 16 rows x 64 cols

    int am = m0 + arow;
    const float* Aptr = nullptr;
    if (am < cnt) {
        int r = rows ? rows[base + am] : (base + am);
        Aptr = A + (size_t)r * lda + acol;
    }
    const float* Bptr = W + (size_t)brow * N + n0 + bcol;

    int ty = tid >> 4, tx = tid & 15;
    float acc[4][4] = {};

    for (int k0 = 0; k0 < Kd; k0 += 16) {
        float4 a4 = Aptr ? *(const float4*)(Aptr + k0)
                         : make_float4(0.f, 0.f, 0.f, 0.f);
        float4 b4 = *(const float4*)(Bptr + (size_t)k0 * N);
        __syncthreads();
        As[acol + 0][arow] = a4.x;
        As[acol + 1][arow] = a4.y;
        As[acol + 2][arow] = a4.z;
        As[acol + 3][arow] = a4.w;
        *(float4*)&Bs[brow][bcol] = b4;
        __syncthreads();
#pragma unroll
        for (int k = 0; k < 16; ++k) {
            float a0 = As[k][(ty << 2) + 0];
            float a1 = As[k][(ty << 2) + 1];
            float a2 = As[k][(ty << 2) + 2];
            float a3 = As[k][(ty << 2) + 3];
            float4 b = *(const float4*)&Bs[k][tx << 2];
            acc[0][0] = fmaf(a0, b.x, acc[0][0]);
            acc[0][1] = fmaf(a0, b.y, acc[0][1]);
            acc[0][2] = fmaf(a0, b.z, acc[0][2]);
            acc[0][3] = fmaf(a0, b.w, acc[0][3]);
            acc[1][0] = fmaf(a1, b.x, acc[1][0]);
            acc[1][1] = fmaf(a1, b.y, acc[1][1]);
            acc[1][2] = fmaf(a1, b.z, acc[1][2]);
            acc[1][3] = fmaf(a1, b.w, acc[1][3]);
            acc[2][0] = fmaf(a2, b.x, acc[2][0]);
            acc[2][1] = fmaf(a2, b.y, acc[2][1]);
            acc[2][2] = fmaf(a2, b.z, acc[2][2]);
            acc[2][3] = fmaf(a2, b.w, acc[2][3]);
            acc[3][0] = fmaf(a3, b.x, acc[3][0]);
            acc[3][1] = fmaf(a3, b.y, acc[3][1]);
            acc[3][2] = fmaf(a3, b.z, acc[3][2]);
            acc[3][3] = fmaf(a3, b.w, acc[3][3]);
        }
    }

#pragma unroll
    for (int i = 0; i < 4; ++i) {
        int m = m0 + (ty << 2) + i;
        if (m < cnt) {
            float* crow = C + (size_t)(base + m) * ldc + n0 + (tx << 2);
#pragma unroll
            for (int j = 0; j < 4; ++j) {
                float vv = acc[i][j] + bv[n0 + (tx << 2) + j];
                if (GELU)
                    vv = 0.5f * vv * (1.0f + erff(vv * 0.70710678118654752f));
                crow[j] = vv;
            }
        }
    }
}

// ---------------- combine: out += sum_k w_k * Y[pos_k] ----------------
__global__ void __launch_bounds__(256) k_combine(float* __restrict__ out) {
    int t = blockIdx.x;
    int i = threadIdx.x;  // 256 threads, float4 each -> 1024 floats
    float w0 = g_tok_w[t * 3 + 0];
    float w1 = g_tok_w[t * 3 + 1];
    float w2 = g_tok_w[t * 3 + 2];
    size_t p0 = (size_t)g_tok_pos[t * 3 + 0];
    size_t p1 = (size_t)g_tok_pos[t * 3 + 1];
    size_t p2 = (size_t)g_tok_pos[t * 3 + 2];
    const float4* Y = (const float4*)g_Y;
    float4* o = (float4*)out + (size_t)t * (D_IN / 4);
    float4 a  = o[i];
    float4 v0 = Y[p0 * (D_IN / 4) + i];
    float4 v1 = Y[p1 * (D_IN / 4) + i];
    float4 v2 = Y[p2 * (D_IN / 4) + i];
    a.x += w0 * v0.x + w1 * v1.x + w2 * v2.x;
    a.y += w0 * v0.y + w1 * v1.y + w2 * v2.y;
    a.z += w0 * v0.z + w1 * v1.z + w2 * v2.z;
    a.w += w0 * v0.w + w1 * v1.w + w2 * v2.w;
    o[i] = a;
}

// ---------------- aux loss + counts ----------------
__global__ void k_final(float* __restrict__ out) {
    int lane = threadIdx.x;
    float v = 0.f;
    if (lane < NE) {
        float P = g_Psum[lane] / (float)T_TOK;
        float F = (float)NE * (float)g_counts[lane] / (float)(TOPK * T_TOK);
        v = P * F;
        out[(size_t)T_TOK * D_IN + 1 + lane] = (float)g_counts[lane];
    }
#pragma unroll
    for (int o = 16; o > 0; o >>= 1) v += __shfl_xor_sync(0xffffffffu, v, o);
    if (lane == 0) out[(size_t)T_TOK * D_IN] = v;
}

// ---------------- host ----------------
extern "C" void kernel_launch(void* const* d_in, const int* in_sizes, int n_in,
                              void* d_out, int out_size) {
    const float* x    = (const float*)d_in[0];
    const float* gW   = (const float*)d_in[1];
    const float* gb   = (const float*)d_in[2];
    const float* bias = (const float*)d_in[3];
    const float* W1   = (const float*)d_in[4];
    const float* b1   = (const float*)d_in[5];
    const float* W2   = (const float*)d_in[6];
    const float* b2   = (const float*)d_in[7];
    const float* sW1  = (const float*)d_in[8];
    const float* sb1  = (const float*)d_in[9];
    const float* sW2  = (const float*)d_in[10];
    const float* sb2  = (const float*)d_in[11];
    float* out = (float*)d_out;

    // resolve scratch symbol addresses (host API, not a stream op; capture-safe)
    float *pH, *pY, *pHs;
    int *pRows, *pOffs, *pSoffs;
    cudaGetSymbolAddress((void**)&pH,     g_H);
    cudaGetSymbolAddress((void**)&pY,     g_Y);
    cudaGetSymbolAddress((void**)&pHs,    g_Hs);
    cudaGetSymbolAddress((void**)&pRows,  g_rows);
    cudaGetSymbolAddress((void**)&pOffs,  g_offs);
    cudaGetSymbolAddress((void**)&pSoffs, g_soffs);

    k_zero<<<1, 32>>>();
    k_gate<<<T_TOK / 8, 256>>>(x, gW, gb, bias);
    k_prefix<<<1, 1>>>();
    k_scatter<<<T_TOK / 256, 256>>>();

    // expert GEMM1: gather x rows -> gelu -> g_H   [P, 768]
    k_gemm<true><<<dim3(H_HID / 64, T_TOK / 64, NE), 256>>>(
        x, pRows, D_IN, W1, (size_t)D_IN * H_HID, b1, H_HID,
        pH, H_HID, pOffs, D_IN, H_HID);
    // expert GEMM2: g_H -> g_Y   [P, 1024]
    k_gemm<false><<<dim3(D_IN / 64, T_TOK / 64, NE), 256>>>(
        pH, nullptr, H_HID, W2, (size_t)H_HID * D_IN, b2, D_IN,
        pY, D_IN, pOffs, H_HID, D_IN);
    // shared GEMM1: x -> gelu -> g_Hs
    k_gemm<true><<<dim3(H_HID / 64, T_TOK / 64, 1), 256>>>(
        x, nullptr, D_IN, sW1, 0, sb1, 0,
        pHs, H_HID, pSoffs, D_IN, H_HID);
    // shared GEMM2: g_Hs -> out (direct write)
    k_gemm<false><<<dim3(D_IN / 64, T_TOK / 64, 1), 256>>>(
        pHs, nullptr, H_HID, sW2, 0, sb2, 0,
        out, D_IN, pSoffs, H_HID, D_IN);

    // out += weighted expert outputs
    k_combine<<<T_TOK, 256>>>(out);

    if (out_size >= T_TOK * D_IN + 1 + NE)
        k_final<<<1, 32>>>(out);
}

// round 7
// speedup vs baseline: 1.8356x; 1.8356x over previous
#include <cuda_runtime.h>
#include <cuda_bf16.h>
#include <math.h>
#include <stdint.h>

#define T_TOK 4096
#define D_IN  1024
#define H_HID 768
#define NE    23
#define TOPK  3
#define P_TOT (T_TOK * TOPK)

// ---------------- portable PTX helpers (sm_75/sm_80-era only) ----------------
__device__ __forceinline__ uint32_t smem_u32(const void* p) {
    uint32_t a;
    asm("{ .reg .u64 t; cvta.to.shared.u64 t, %1; cvt.u32.u64 %0, t; }" : "=r"(a) : "l"(p));
    return a;
}
#define LDSM_X4(r, addr) \
    asm volatile("ldmatrix.sync.aligned.m8n8.x4.shared.b16 {%0,%1,%2,%3}, [%4];" \
                 : "=r"((r)[0]), "=r"((r)[1]), "=r"((r)[2]), "=r"((r)[3]) : "r"(addr))

#define MMA16816(c, a, b0, b1) \
    asm volatile("mma.sync.aligned.m16n8k16.row.col.f32.bf16.bf16.f32 " \
                 "{%0,%1,%2,%3}, {%4,%5,%6,%7}, {%8,%9}, {%0,%1,%2,%3};" \
                 : "+f"((c)[0]), "+f"((c)[1]), "+f"((c)[2]), "+f"((c)[3]) \
                 : "r"((a)[0]), "r"((a)[1]), "r"((a)[2]), "r"((a)[3]), "r"(b0), "r"(b1))

// ---------------- scratch ----------------
__device__ __align__(16) __nv_bfloat16 g_xhi[(size_t)T_TOK * D_IN];
__device__ __align__(16) __nv_bfloat16 g_xlo[(size_t)T_TOK * D_IN];
__device__ __align__(16) __nv_bfloat16 g_W1t_hi[(size_t)NE * H_HID * D_IN]; // [E][N=768][K=1024]
__device__ __align__(16) __nv_bfloat16 g_W1t_lo[(size_t)NE * H_HID * D_IN];
__device__ __align__(16) __nv_bfloat16 g_W2t_hi[(size_t)NE * D_IN * H_HID]; // [E][N=1024][K=768]
__device__ __align__(16) __nv_bfloat16 g_W2t_lo[(size_t)NE * D_IN * H_HID];
__device__ __align__(16) __nv_bfloat16 g_s1t_hi[(size_t)H_HID * D_IN];
__device__ __align__(16) __nv_bfloat16 g_s1t_lo[(size_t)H_HID * D_IN];
__device__ __align__(16) __nv_bfloat16 g_s2t_hi[(size_t)D_IN * H_HID];
__device__ __align__(16) __nv_bfloat16 g_s2t_lo[(size_t)D_IN * H_HID];
__device__ __align__(16) __nv_bfloat16 g_Hhi[(size_t)P_TOT * H_HID];
__device__ __align__(16) __nv_bfloat16 g_Hlo[(size_t)P_TOT * H_HID];
__device__ __align__(16) __nv_bfloat16 g_Hshi[(size_t)T_TOK * H_HID];
__device__ __align__(16) __nv_bfloat16 g_Hslo[(size_t)T_TOK * H_HID];
__device__ __align__(16) float g_Y[(size_t)P_TOT * D_IN];
__device__ int   g_rows[P_TOT];
__device__ int   g_tok_e[P_TOT];
__device__ float g_tok_w[P_TOT];
__device__ int   g_tok_pos[P_TOT];
__device__ int   g_counts[NE];
__device__ int   g_cursor[NE];
__device__ int   g_offs[NE + 1];
__device__ float g_Psum[NE];
__device__ int   g_soffs[2];

// ---------------- init ----------------
__global__ void k_zero() {
    int i = threadIdx.x;
    if (i < NE) { g_counts[i] = 0; g_cursor[i] = 0; g_Psum[i] = 0.f; }
    if (i == 0) { g_soffs[0] = 0; g_soffs[1] = T_TOK; }
}

// ---------------- gating ----------------
__global__ void __launch_bounds__(256) k_gate(const float* __restrict__ x,
                                              const float* __restrict__ gW,
                                              const float* __restrict__ gb,
                                              const float* __restrict__ bias) {
    __shared__ float xs[8][D_IN];
    __shared__ float sg[8][NE + 1];
    __shared__ float ss[8][NE + 1];
    int tid = threadIdx.x;
    int t0 = blockIdx.x * 8;
    for (int i = tid; i < 8 * D_IN; i += 256)
        ((float*)xs)[i] = x[(size_t)t0 * D_IN + i];
    __syncthreads();

    int w = tid >> 5, lane = tid & 31;
    int t = t0 + w;

    float gate = 0.f;
    if (lane < NE) {
        float acc = 0.f;
#pragma unroll 4
        for (int d = 0; d < D_IN; ++d)
            acc = fmaf(xs[w][d], gW[d * NE + lane], acc);
        acc += gb[lane];
        gate = 1.0f / (1.0f + expf(-acc));
        sg[w][lane] = gate;
        ss[w][lane] = gate + bias[lane];
    }
    float v = (lane < NE) ? gate : 0.f;
#pragma unroll
    for (int o = 16; o > 0; o >>= 1) v += __shfl_xor_sync(0xffffffffu, v, o);
    if (lane < NE) atomicAdd(&g_Psum[lane], gate / v);
    __syncwarp();

    if (lane == 0) {
        int idx[TOPK]; float wv[TOPK]; bool used[NE];
#pragma unroll
        for (int e = 0; e < NE; ++e) used[e] = false;
        float wsum = 0.f;
        for (int k = 0; k < TOPK; ++k) {
            int best = 0; float bs = -1e30f;
            for (int e = 0; e < NE; ++e)
                if (!used[e] && ss[w][e] > bs) { bs = ss[w][e]; best = e; }
            used[best] = true;
            idx[k] = best; wv[k] = sg[w][best]; wsum += wv[k];
        }
        for (int k = 0; k < TOPK; ++k) {
            g_tok_e[t * TOPK + k] = idx[k];
            g_tok_w[t * TOPK + k] = wv[k] / wsum;
            atomicAdd(&g_counts[idx[k]], 1);
        }
    }
}

__global__ void k_prefix() {
    int o = 0;
    g_offs[0] = 0;
    for (int e = 0; e < NE; ++e) { o += g_counts[e]; g_offs[e + 1] = o; }
}

__global__ void k_scatter() {
    int t = blockIdx.x * blockDim.x + threadIdx.x;
    if (t >= T_TOK) return;
#pragma unroll
    for (int k = 0; k < TOPK; ++k) {
        int e = g_tok_e[t * TOPK + k];
        int p = g_offs[e] + atomicAdd(&g_cursor[e], 1);
        g_rows[p] = t;
        g_tok_pos[t * TOPK + k] = p;
    }
}

// ---------------- conversions ----------------
__device__ __forceinline__ void split_bf16(float v, __nv_bfloat16& hi, __nv_bfloat16& lo) {
    hi = __float2bfloat16_rn(v);
    lo = __float2bfloat16_rn(v - __bfloat162float(hi));
}

__global__ void __launch_bounds__(256) k_convx(const float* __restrict__ x,
                                               __nv_bfloat16* __restrict__ xhi,
                                               __nv_bfloat16* __restrict__ xlo) {
    size_t i = ((size_t)blockIdx.x * 256 + threadIdx.x) * 4;
    float4 v = *(const float4*)(x + i);
    __nv_bfloat16 h[4], l[4];
    split_bf16(v.x, h[0], l[0]); split_bf16(v.y, h[1], l[1]);
    split_bf16(v.z, h[2], l[2]); split_bf16(v.w, h[3], l[3]);
    *(uint2*)(xhi + i) = *(uint2*)h;
    *(uint2*)(xlo + i) = *(uint2*)l;
}

// transpose W[e][K][N] -> Wt[e][N][K] with hi/lo split
__global__ void __launch_bounds__(256) k_convW(const float* __restrict__ W,
                                               __nv_bfloat16* __restrict__ Whi,
                                               __nv_bfloat16* __restrict__ Wlo,
                                               int Kd, int N) {
    __shared__ float ts[32][33];
    int e = blockIdx.z;
    const float* Wp = W + (size_t)e * Kd * N;
    int n0 = blockIdx.x * 32, k0 = blockIdx.y * 32;
    int tx = threadIdx.x & 31, ty = threadIdx.x >> 5;
    for (int i = ty; i < 32; i += 8)
        ts[i][tx] = Wp[(size_t)(k0 + i) * N + n0 + tx];
    __syncthreads();
    size_t ob = (size_t)e * N * Kd;
    for (int i = ty; i < 32; i += 8) {
        float v = ts[tx][i];
        __nv_bfloat16 h, l; split_bf16(v, h, l);
        size_t o = ob + (size_t)(n0 + i) * Kd + k0 + tx;
        Whi[o] = h; Wlo[o] = l;
    }
}

// ================= grouped GEMM via mma.sync (bf16 hi/lo, 3-pass) =================
// CTA tile 128x128, k-chunk 32, 8 warps (4M x 2N), warptile 32x64.
// Single SMEM stage, register-prefetch software pipeline (no cp.async).
#define AS_STRIDE 40
#define E_A_HI 0
#define E_A_LO (128 * AS_STRIDE)
#define E_B_HI (2 * 128 * AS_STRIDE)
#define E_B_LO (3 * 128 * AS_STRIDE)
#define E_STAGE (4 * 128 * AS_STRIDE)          // 20480 bf16 = 40960 B
#define SMEM_GEMM_SZ (E_STAGE * 2 + 512)       // stage + 128 row ints

template <int MODE> // 0: bias+GELU -> (Chi,Clo) bf16 ; 1: bias -> Cf fp32
__global__ void __launch_bounds__(256) k_mma_gemm(
    const __nv_bfloat16* __restrict__ Ahi, const __nv_bfloat16* __restrict__ Alo,
    const int* __restrict__ rows, int lda,
    const __nv_bfloat16* __restrict__ Bhi, const __nv_bfloat16* __restrict__ Blo,
    size_t wstride,
    const float* __restrict__ biasg, int bstride,
    float* __restrict__ Cf,
    __nv_bfloat16* __restrict__ Chi, __nv_bfloat16* __restrict__ Clo,
    int ldc,
    const int* __restrict__ offs, int Kd, int N)
{
    int e    = blockIdx.z;
    int base = offs[e];
    int cnt  = offs[e + 1] - base;
    int m0   = blockIdx.y * 128;
    if (m0 >= cnt) return;
    int n0   = blockIdx.x * 128;

    extern __shared__ __nv_bfloat16 smem[];
    int* rows_s = (int*)((char*)smem + E_STAGE * 2);
    uint32_t sb = smem_u32(smem);

    int tid = threadIdx.x, wid = tid >> 5, lane = tid & 31;

    if (tid < 128) {
        int m = m0 + tid;
        rows_s[tid] = (m < cnt) ? (rows ? rows[base + m] : base + m) : -1;
    }
    __syncthreads();

    const __nv_bfloat16* Bhe = Bhi + (size_t)e * wstride;
    const __nv_bfloat16* Ble = Blo + (size_t)e * wstride;

    // loader: thread covers 2 float4 per tensor; both share row = tid>>1
    const int lrow = tid >> 1;
    const int lq   = (tid & 1) * 2;
    const int arow_ld = rows_s[lrow];
    const size_t a_base = (size_t)(arow_ld < 0 ? 0 : arow_ld) * lda + lq * 8;
    const size_t b_base = (size_t)(n0 + lrow) * Kd + lq * 8;

    const int nc = Kd >> 5;

    int wm = wid & 3, wn = wid >> 2;
    int m_warp = wm * 32, n_warp = wn * 64;

    float acc[2][8][4];
#pragma unroll
    for (int i = 0; i < 2; ++i)
#pragma unroll
        for (int j = 0; j < 8; ++j)
#pragma unroll
            for (int q = 0; q < 4; ++q) acc[i][j][q] = 0.f;

    // ldmatrix address components (elems)
    int a_row = ((lane >> 3) & 1) * 8 + (lane & 7);
    int a_col = (lane >> 4) * 8;
    int b_row = (lane >> 4) * 8 + (lane & 7);
    int b_col = ((lane >> 3) & 1) * 8;

    const float4 fz = make_float4(0.f, 0.f, 0.f, 0.f);
    float4 pa_h[2], pa_l[2], pb_h[2], pb_l[2];

    // prefetch chunk 0
#pragma unroll
    for (int j = 0; j < 2; ++j) {
        if (arow_ld >= 0) {
            pa_h[j] = *(const float4*)(Ahi + a_base + j * 8);
            pa_l[j] = *(const float4*)(Alo + a_base + j * 8);
        } else { pa_h[j] = fz; pa_l[j] = fz; }
        pb_h[j] = *(const float4*)(Bhe + b_base + j * 8);
        pb_l[j] = *(const float4*)(Ble + b_base + j * 8);
    }

    for (int c = 0; c < nc; ++c) {
        if (c) __syncthreads();   // previous compute done before overwriting SMEM
#pragma unroll
        for (int j = 0; j < 2; ++j) {
            uint32_t so = (uint32_t)(lrow * AS_STRIDE + (lq + j) * 8) * 2;
            *(float4*)((char*)smem + (E_A_HI * 2) + so) = pa_h[j];
            *(float4*)((char*)smem + (E_A_LO * 2) + so) = pa_l[j];
            *(float4*)((char*)smem + (E_B_HI * 2) + so) = pb_h[j];
            *(float4*)((char*)smem + (E_B_LO * 2) + so) = pb_l[j];
        }
        __syncthreads();

        if (c + 1 < nc) {         // prefetch next chunk while computing this one
            int c0 = (c + 1) << 5;
#pragma unroll
            for (int j = 0; j < 2; ++j) {
                if (arow_ld >= 0) {
                    pa_h[j] = *(const float4*)(Ahi + a_base + c0 + j * 8);
                    pa_l[j] = *(const float4*)(Alo + a_base + c0 + j * 8);
                } else { pa_h[j] = fz; pa_l[j] = fz; }
                pb_h[j] = *(const float4*)(Bhe + b_base + c0 + j * 8);
                pb_l[j] = *(const float4*)(Ble + b_base + c0 + j * 8);
            }
        }

#pragma unroll
        for (int ks = 0; ks < 32; ks += 16) {
            uint32_t a_hi[2][4], a_lo[2][4], bq[4][4];
#pragma unroll
            for (int mi = 0; mi < 2; ++mi) {
                uint32_t ra = (uint32_t)(E_A_HI + (m_warp + mi * 16 + a_row) * AS_STRIDE + ks + a_col) * 2;
                LDSM_X4(a_hi[mi], sb + ra);
                uint32_t rl = (uint32_t)(E_A_LO + (m_warp + mi * 16 + a_row) * AS_STRIDE + ks + a_col) * 2;
                LDSM_X4(a_lo[mi], sb + rl);
            }
#pragma unroll
            for (int g = 0; g < 4; ++g) {
                uint32_t rb = (uint32_t)(E_B_HI + (n_warp + g * 16 + b_row) * AS_STRIDE + ks + b_col) * 2;
                LDSM_X4(bq[g], sb + rb);
            }
#pragma unroll
            for (int mi = 0; mi < 2; ++mi)
#pragma unroll
                for (int g = 0; g < 4; ++g) {
                    MMA16816(acc[mi][2 * g],     a_hi[mi], bq[g][0], bq[g][1]);
                    MMA16816(acc[mi][2 * g + 1], a_hi[mi], bq[g][2], bq[g][3]);
                    MMA16816(acc[mi][2 * g],     a_lo[mi], bq[g][0], bq[g][1]);
                    MMA16816(acc[mi][2 * g + 1], a_lo[mi], bq[g][2], bq[g][3]);
                }
#pragma unroll
            for (int g = 0; g < 4; ++g) {
                uint32_t rb = (uint32_t)(E_B_LO + (n_warp + g * 16 + b_row) * AS_STRIDE + ks + b_col) * 2;
                LDSM_X4(bq[g], sb + rb);
            }
#pragma unroll
            for (int mi = 0; mi < 2; ++mi)
#pragma unroll
                for (int g = 0; g < 4; ++g) {
                    MMA16816(acc[mi][2 * g],     a_hi[mi], bq[g][0], bq[g][1]);
                    MMA16816(acc[mi][2 * g + 1], a_hi[mi], bq[g][2], bq[g][3]);
                }
        }
    }

    // ---------------- epilogue ----------------
    const float* bv = biasg + (size_t)e * bstride;
    int qrow = lane >> 2, qcol = (lane & 3) * 2;
#pragma unroll
    for (int mi = 0; mi < 2; ++mi) {
#pragma unroll
        for (int nj = 0; nj < 8; ++nj) {
            int col = n0 + n_warp + nj * 8 + qcol;
            float2 bb = *(const float2*)(bv + col);
#pragma unroll
            for (int half = 0; half < 2; ++half) {
                int lm = m0 + m_warp + mi * 16 + qrow + half * 8;
                if (lm < cnt) {
                    size_t gm = (size_t)(base + lm);
                    float v0 = acc[mi][nj][2 * half + 0] + bb.x;
                    float v1 = acc[mi][nj][2 * half + 1] + bb.y;
                    if (MODE == 0) {
                        v0 = 0.5f * v0 * (1.0f + erff(v0 * 0.70710678118654752f));
                        v1 = 0.5f * v1 * (1.0f + erff(v1 * 0.70710678118654752f));
                        __nv_bfloat16 h2[2], l2[2];
                        split_bf16(v0, h2[0], l2[0]);
                        split_bf16(v1, h2[1], l2[1]);
                        *(uint32_t*)(Chi + gm * ldc + col) = *(uint32_t*)h2;
                        *(uint32_t*)(Clo + gm * ldc + col) = *(uint32_t*)l2;
                    } else {
                        *(float2*)(Cf + gm * ldc + col) = make_float2(v0, v1);
                    }
                }
            }
        }
    }
}

// ---------------- combine + final ----------------
__global__ void __launch_bounds__(256) k_combine(float* __restrict__ out) {
    int t = blockIdx.x;
    int i = threadIdx.x;
    float w0 = g_tok_w[t * 3 + 0];
    float w1 = g_tok_w[t * 3 + 1];
    float w2 = g_tok_w[t * 3 + 2];
    size_t p0 = (size_t)g_tok_pos[t * 3 + 0];
    size_t p1 = (size_t)g_tok_pos[t * 3 + 1];
    size_t p2 = (size_t)g_tok_pos[t * 3 + 2];
    const float4* Y = (const float4*)g_Y;
    float4* o = (float4*)out + (size_t)t * (D_IN / 4);
    float4 a  = o[i];
    float4 v0 = Y[p0 * (D_IN / 4) + i];
    float4 v1 = Y[p1 * (D_IN / 4) + i];
    float4 v2 = Y[p2 * (D_IN / 4) + i];
    a.x += w0 * v0.x + w1 * v1.x + w2 * v2.x;
    a.y += w0 * v0.y + w1 * v1.y + w2 * v2.y;
    a.z += w0 * v0.z + w1 * v1.z + w2 * v2.z;
    a.w += w0 * v0.w + w1 * v1.w + w2 * v2.w;
    o[i] = a;
}

__global__ void k_final(float* __restrict__ out) {
    int lane = threadIdx.x;
    float v = 0.f;
    if (lane < NE) {
        float P = g_Psum[lane] / (float)T_TOK;
        float F = (float)NE * (float)g_counts[lane] / (float)(TOPK * T_TOK);
        v = P * F;
        out[(size_t)T_TOK * D_IN + 1 + lane] = (float)g_counts[lane];
    }
#pragma unroll
    for (int o = 16; o > 0; o >>= 1) v += __shfl_xor_sync(0xffffffffu, v, o);
    if (lane == 0) out[(size_t)T_TOK * D_IN] = v;
}

// ---------------- host ----------------
extern "C" void kernel_launch(void* const* d_in, const int* in_sizes, int n_in,
                              void* d_out, int out_size) {
    const float* x    = (const float*)d_in[0];
    const float* gW   = (const float*)d_in[1];
    const float* gb   = (const float*)d_in[2];
    const float* bias = (const float*)d_in[3];
    const float* W1   = (const float*)d_in[4];
    const float* b1   = (const float*)d_in[5];
    const float* W2   = (const float*)d_in[6];
    const float* b2   = (const float*)d_in[7];
    const float* sW1  = (const float*)d_in[8];
    const float* sb1  = (const float*)d_in[9];
    const float* sW2  = (const float*)d_in[10];
    const float* sb2  = (const float*)d_in[11];
    float* out = (float*)d_out;

    cudaFuncSetAttribute(k_mma_gemm<0>, cudaFuncAttributeMaxDynamicSharedMemorySize, SMEM_GEMM_SZ);
    cudaFuncSetAttribute(k_mma_gemm<1>, cudaFuncAttributeMaxDynamicSharedMemorySize, SMEM_GEMM_SZ);

    __nv_bfloat16 *pxhi, *pxlo, *pW1h, *pW1l, *pW2h, *pW2l, *ps1h, *ps1l, *ps2h, *ps2l;
    __nv_bfloat16 *pHhi, *pHlo, *pHsh, *pHsl;
    float* pY;
    int *pRows, *pOffs, *pSoffs;
    cudaGetSymbolAddress((void**)&pxhi, g_xhi);    cudaGetSymbolAddress((void**)&pxlo, g_xlo);
    cudaGetSymbolAddress((void**)&pW1h, g_W1t_hi); cudaGetSymbolAddress((void**)&pW1l, g_W1t_lo);
    cudaGetSymbolAddress((void**)&pW2h, g_W2t_hi); cudaGetSymbolAddress((void**)&pW2l, g_W2t_lo);
    cudaGetSymbolAddress((void**)&ps1h, g_s1t_hi); cudaGetSymbolAddress((void**)&ps1l, g_s1t_lo);
    cudaGetSymbolAddress((void**)&ps2h, g_s2t_hi); cudaGetSymbolAddress((void**)&ps2l, g_s2t_lo);
    cudaGetSymbolAddress((void**)&pHhi, g_Hhi);    cudaGetSymbolAddress((void**)&pHlo, g_Hlo);
    cudaGetSymbolAddress((void**)&pHsh, g_Hshi);   cudaGetSymbolAddress((void**)&pHsl, g_Hslo);
    cudaGetSymbolAddress((void**)&pY, g_Y);
    cudaGetSymbolAddress((void**)&pRows, g_rows);
    cudaGetSymbolAddress((void**)&pOffs, g_offs);
    cudaGetSymbolAddress((void**)&pSoffs, g_soffs);

    k_zero<<<1, 32>>>();
    k_gate<<<T_TOK / 8, 256>>>(x, gW, gb, bias);
    k_prefix<<<1, 1>>>();
    k_scatter<<<T_TOK / 256, 256>>>();

    // conversions
    k_convx<<<(T_TOK * D_IN / 4) / 256, 256>>>(x, pxhi, pxlo);
    k_convW<<<dim3(H_HID / 32, D_IN / 32, NE), 256>>>(W1, pW1h, pW1l, D_IN, H_HID);
    k_convW<<<dim3(D_IN / 32, H_HID / 32, NE), 256>>>(W2, pW2h, pW2l, H_HID, D_IN);
    k_convW<<<dim3(H_HID / 32, D_IN / 32, 1), 256>>>(sW1, ps1h, ps1l, D_IN, H_HID);
    k_convW<<<dim3(D_IN / 32, H_HID / 32, 1), 256>>>(sW2, ps2h, ps2l, H_HID, D_IN);

    // expert GEMM1: x -> gelu -> H (hi/lo)
    k_mma_gemm<0><<<dim3(H_HID / 128, T_TOK / 128, NE), 256, SMEM_GEMM_SZ>>>(
        pxhi, pxlo, pRows, D_IN, pW1h, pW1l, (size_t)H_HID * D_IN,
        b1, H_HID, nullptr, pHhi, pHlo, H_HID, pOffs, D_IN, H_HID);
    // expert GEMM2: H -> Y (fp32)
    k_mma_gemm<1><<<dim3(D_IN / 128, T_TOK / 128, NE), 256, SMEM_GEMM_SZ>>>(
        pHhi, pHlo, nullptr, H_HID, pW2h, pW2l, (size_t)D_IN * H_HID,
        b2, D_IN, pY, nullptr, nullptr, D_IN, pOffs, H_HID, D_IN);
    // shared GEMM1
    k_mma_gemm<0><<<dim3(H_HID / 128, T_TOK / 128, 1), 256, SMEM_GEMM_SZ>>>(
        pxhi, pxlo, nullptr, D_IN, ps1h, ps1l, 0,
        sb1, 0, nullptr, pHsh, pHsl, H_HID, pSoffs, D_IN, H_HID);
    // shared GEMM2 -> out directly
    k_mma_gemm<1><<<dim3(D_IN / 128, T_TOK / 128, 1), 256, SMEM_GEMM_SZ>>>(
        pHsh, pHsl, nullptr, H_HID, ps2h, ps2l, 0,
        sb2, 0, out, nullptr, nullptr, D_IN, pSoffs, H_HID, D_IN);

    k_combine<<<T_TOK, 256>>>(out);

    if (out_size >= T_TOK * D_IN + 1 + NE)
        k_final<<<1, 32>>>(out);
}